// round 1
// baseline (speedup 1.0000x reference)
#include <cuda_runtime.h>
#include <math.h>
#include <float.h>
#include <stdint.h>

#define NN 50000
#define EE 400000
#define EPSV 1e-5f

// ---------------- scratch (static device globals; no allocation) ----------------
__device__ float g_h[(size_t)NN * 512];   // per-head features (largest layer)
__device__ float g_io0[(size_t)NN * 128]; // ping buffer
__device__ float g_io1[(size_t)NN * 128]; // pong buffer
__device__ float g_ls[NN * 4];
__device__ float g_ld[NN * 4];
__device__ float g_logits[NN];
__device__ float g_bn[256];    // [sum(C); sumsq(C)]
__device__ float g_part[256];  // reduction partials
__device__ float g_scal[2];    // max, sum
__device__ int   g_deg[NN];    // also reused as cond flags
__device__ int   g_off[NN + 1];// CSR offsets; reused as positions
__device__ int   g_cur[NN];    // cursors; reused as idx buffer
__device__ int   g_srcs[EE + NN];

// ---------------- threefry2x32 ----------------
__device__ __forceinline__ unsigned rotl32d(unsigned v, int r) {
    return __funnelshift_l(v, v, r);
}
// partitionable 32-bit random bits: out0 ^ out1 of threefry(key, (x0,x1))
__device__ __forceinline__ unsigned tf_xor(unsigned k0, unsigned k1, unsigned x0, unsigned x1) {
    unsigned k2 = k0 ^ k1 ^ 0x1BD11BDAu;
    x0 += k0; x1 += k1;
#define TF_R(r) { x0 += x1; x1 = rotl32d(x1, r); x1 ^= x0; }
    TF_R(13) TF_R(15) TF_R(26) TF_R(6)   x0 += k1; x1 += k2 + 1u;
    TF_R(17) TF_R(29) TF_R(16) TF_R(24)  x0 += k2; x1 += k0 + 2u;
    TF_R(13) TF_R(15) TF_R(26) TF_R(6)   x0 += k0; x1 += k1 + 3u;
    TF_R(17) TF_R(29) TF_R(16) TF_R(24)  x0 += k1; x1 += k2 + 4u;
    TF_R(13) TF_R(15) TF_R(26) TF_R(6)   x0 += k2; x1 += k0 + 5u;
#undef TF_R
    return x0 ^ x1;
}

static inline unsigned rotl32h(unsigned v, int r) { return (v << r) | (v >> (32 - r)); }
static void tf_host(unsigned k0, unsigned k1, unsigned x0, unsigned x1,
                    unsigned* o0, unsigned* o1) {
    unsigned k2 = k0 ^ k1 ^ 0x1BD11BDAu;
    x0 += k0; x1 += k1;
#define TF_RH(r) { x0 += x1; x1 = rotl32h(x1, r); x1 ^= x0; }
    TF_RH(13) TF_RH(15) TF_RH(26) TF_RH(6)   x0 += k1; x1 += k2 + 1u;
    TF_RH(17) TF_RH(29) TF_RH(16) TF_RH(24)  x0 += k2; x1 += k0 + 2u;
    TF_RH(13) TF_RH(15) TF_RH(26) TF_RH(6)   x0 += k0; x1 += k1 + 3u;
    TF_RH(17) TF_RH(29) TF_RH(16) TF_RH(24)  x0 += k1; x1 += k2 + 4u;
    TF_RH(13) TF_RH(15) TF_RH(26) TF_RH(6)   x0 += k2; x1 += k0 + 5u;
#undef TF_RH
    *o0 = x0; *o1 = x1;
}

// ---------------- CSR build ----------------
__global__ void k_init_deg(int* deg, int n) {
    int i = blockIdx.x * blockDim.x + threadIdx.x;
    if (i < n) deg[i] = 1; // self-loop
}
__global__ void k_count(const int* __restrict__ dst, int e, int* deg) {
    int i = blockIdx.x * blockDim.x + threadIdx.x;
    if (i < e) atomicAdd(&deg[dst[i]], 1);
}
__global__ void k_exscan(const int* __restrict__ in, int* __restrict__ out, int n) {
    __shared__ int sh[1024];
    int t = threadIdx.x;
    int carry = 0;
    for (int base = 0; base < n; base += 1024) {
        int v = (base + t < n) ? in[base + t] : 0;
        sh[t] = v;
        __syncthreads();
        for (int o = 1; o < 1024; o <<= 1) {
            int add = (t >= o) ? sh[t - o] : 0;
            __syncthreads();
            sh[t] += add;
            __syncthreads();
        }
        if (base + t < n) out[base + t] = carry + sh[t] - v;
        carry += sh[1023];
        __syncthreads();
    }
    if (t == 0) out[n] = carry;
}
__global__ void k_copy_int(const int* __restrict__ in, int* __restrict__ out, int n) {
    int i = blockIdx.x * blockDim.x + threadIdx.x;
    if (i < n) out[i] = in[i];
}
__global__ void k_scatter(const int* __restrict__ src, const int* __restrict__ dst,
                          int e, int n, int* cur, int* __restrict__ outsrc) {
    int i = blockIdx.x * blockDim.x + threadIdx.x;
    if (i < e) {
        int p = atomicAdd(&cur[dst[i]], 1);
        outsrc[p] = src[i];
    } else if (i < e + n) {
        int nd = i - e;
        int p = atomicAdd(&cur[nd], 1);
        outsrc[p] = nd;
    }
}

// ---------------- GEMM: Y(N,M) = X(N,K)[cols xcol0..] @ W(K,M) (+bias) ----------------
// 16 rows per block, 2 cols per thread, blockDim = M/2, dyn smem = 16*K floats (k-major)
__global__ void k_gemm16x2(const float* __restrict__ X, int ldx, int xcol0,
                           const float* __restrict__ W, const float* __restrict__ bias,
                           float* __restrict__ Y, int K, int M) {
    extern __shared__ float xs[];
    int r0 = blockIdx.x * 16;
    int tid = threadIdx.x, bd = blockDim.x;
    for (int i = tid; i < 16 * K; i += bd) {
        int r = i & 15, k = i >> 4;
        xs[k * 16 + r] = X[(size_t)(r0 + r) * ldx + xcol0 + k];
    }
    __syncthreads();
    int j0 = tid, j1 = tid + bd;
    float acc0[16], acc1[16];
    float b0 = bias ? bias[j0] : 0.f;
    float b1 = bias ? bias[j1] : 0.f;
#pragma unroll
    for (int r = 0; r < 16; r++) { acc0[r] = b0; acc1[r] = b1; }
    for (int k = 0; k < K; k++) {
        float w0 = W[(size_t)k * M + j0];
        float w1 = W[(size_t)k * M + j1];
        const float4* xp = reinterpret_cast<const float4*>(xs + k * 16);
        float4 q0 = xp[0], q1 = xp[1], q2 = xp[2], q3 = xp[3];
        float xv[16] = {q0.x, q0.y, q0.z, q0.w, q1.x, q1.y, q1.z, q1.w,
                        q2.x, q2.y, q2.z, q2.w, q3.x, q3.y, q3.z, q3.w};
#pragma unroll
        for (int r = 0; r < 16; r++) {
            acc0[r] = fmaf(xv[r], w0, acc0[r]);
            acc1[r] = fmaf(xv[r], w1, acc1[r]);
        }
    }
    for (int r = 0; r < 16; r++) {
        Y[(size_t)(r0 + r) * M + j0] = acc0[r];
        Y[(size_t)(r0 + r) * M + j1] = acc1[r];
    }
}

// ---------------- attention coefficients ls/ld ----------------
__global__ void k_attn_coef(const float* __restrict__ h, const float* __restrict__ as_,
                            const float* __restrict__ ad_, float* __restrict__ ls,
                            float* __restrict__ ld, int C) {
    int n = blockIdx.x;
    int w = threadIdx.x >> 5, lane = threadIdx.x & 31;
    const float* hr = h + (size_t)n * 4 * C + w * C;
    float s = 0.f, d = 0.f;
    for (int c = lane; c < C; c += 32) {
        float v = hr[c];
        s = fmaf(v, as_[w * C + c], s);
        d = fmaf(v, ad_[w * C + c], d);
    }
#pragma unroll
    for (int o = 16; o > 0; o >>= 1) {
        s += __shfl_down_sync(0xffffffffu, s, o);
        d += __shfl_down_sync(0xffffffffu, d, o);
    }
    if (lane == 0) { ls[n * 4 + w] = s; ld[n * 4 + w] = d; }
}

__device__ __forceinline__ float lrelu02(float v) { return v > 0.f ? v : 0.2f * v; }

// ---------------- GAT aggregation per dst node (blockDim = C) ----------------
__global__ void k_gat_aggregate(const float* __restrict__ h, const float* __restrict__ ls,
                                const float* __restrict__ ldv, const int* __restrict__ off,
                                const int* __restrict__ srcs, const float* __restrict__ bias,
                                float* __restrict__ out, int C) {
    int n = blockIdx.x;
    int t = threadIdx.x;
    int start = off[n], end = off[n + 1];
    __shared__ float s_ld[4], s_m[4], s_den[4];
    if (t < 4) s_ld[t] = ldv[n * 4 + t];
    __syncthreads();
    if (t < 32) {
        float m0 = -FLT_MAX, m1 = -FLT_MAX, m2 = -FLT_MAX, m3 = -FLT_MAX;
        for (int e = start + t; e < end; e += 32) {
            int s = srcs[e];
            float4 lv = *reinterpret_cast<const float4*>(ls + s * 4);
            m0 = fmaxf(m0, lrelu02(lv.x + s_ld[0]));
            m1 = fmaxf(m1, lrelu02(lv.y + s_ld[1]));
            m2 = fmaxf(m2, lrelu02(lv.z + s_ld[2]));
            m3 = fmaxf(m3, lrelu02(lv.w + s_ld[3]));
        }
#pragma unroll
        for (int o = 16; o > 0; o >>= 1) {
            m0 = fmaxf(m0, __shfl_xor_sync(0xffffffffu, m0, o));
            m1 = fmaxf(m1, __shfl_xor_sync(0xffffffffu, m1, o));
            m2 = fmaxf(m2, __shfl_xor_sync(0xffffffffu, m2, o));
            m3 = fmaxf(m3, __shfl_xor_sync(0xffffffffu, m3, o));
        }
        if (t == 0) { s_m[0] = m0; s_m[1] = m1; s_m[2] = m2; s_m[3] = m3; }
    }
    __syncthreads();
    if (t < 32) {
        float d0 = 0.f, d1 = 0.f, d2 = 0.f, d3 = 0.f;
        for (int e = start + t; e < end; e += 32) {
            int s = srcs[e];
            float4 lv = *reinterpret_cast<const float4*>(ls + s * 4);
            d0 += expf(lrelu02(lv.x + s_ld[0]) - s_m[0]);
            d1 += expf(lrelu02(lv.y + s_ld[1]) - s_m[1]);
            d2 += expf(lrelu02(lv.z + s_ld[2]) - s_m[2]);
            d3 += expf(lrelu02(lv.w + s_ld[3]) - s_m[3]);
        }
#pragma unroll
        for (int o = 16; o > 0; o >>= 1) {
            d0 += __shfl_xor_sync(0xffffffffu, d0, o);
            d1 += __shfl_xor_sync(0xffffffffu, d1, o);
            d2 += __shfl_xor_sync(0xffffffffu, d2, o);
            d3 += __shfl_xor_sync(0xffffffffu, d3, o);
        }
        if (t == 0) { s_den[0] = d0; s_den[1] = d1; s_den[2] = d2; s_den[3] = d3; }
    }
    __syncthreads();
    float ld0 = s_ld[0], ld1 = s_ld[1], ld2 = s_ld[2], ld3 = s_ld[3];
    float mm0 = s_m[0], mm1 = s_m[1], mm2 = s_m[2], mm3 = s_m[3];
    float rd0 = 1.f / s_den[0], rd1 = 1.f / s_den[1], rd2 = 1.f / s_den[2], rd3 = 1.f / s_den[3];
    float a0 = 0.f, a1 = 0.f, a2 = 0.f, a3 = 0.f;
    for (int e = start; e < end; e++) {
        int s = srcs[e];
        float4 lv = *reinterpret_cast<const float4*>(ls + s * 4);
        float al0 = expf(lrelu02(lv.x + ld0) - mm0) * rd0;
        float al1 = expf(lrelu02(lv.y + ld1) - mm1) * rd1;
        float al2 = expf(lrelu02(lv.z + ld2) - mm2) * rd2;
        float al3 = expf(lrelu02(lv.w + ld3) - mm3) * rd3;
        const float* hr = h + (size_t)s * 4 * C;
        a0 = fmaf(hr[t], al0, a0);
        a1 = fmaf(hr[C + t], al1, a1);
        a2 = fmaf(hr[2 * C + t], al2, a2);
        a3 = fmaf(hr[3 * C + t], al3, a3);
    }
    out[(size_t)n * C + t] = 0.25f * (a0 + a1 + a2 + a3) + bias[t];
}

// ---------------- BatchNorm ----------------
__global__ void k_zero256(float* p) { p[threadIdx.x] = 0.f; }
__global__ void k_bn_stats(const float* __restrict__ x, int N, int C, float* __restrict__ sums) {
    int t = threadIdx.x;
    int r0 = blockIdx.x * 256;
    int r1 = min(r0 + 256, N);
    float s = 0.f, q = 0.f;
    for (int r = r0; r < r1; r++) {
        float v = x[(size_t)r * C + t];
        s += v; q = fmaf(v, v, q);
    }
    atomicAdd(&sums[t], s);
    atomicAdd(&sums[C + t], q);
}
__global__ void k_bn_apply(float* __restrict__ x, int N, int C,
                           const float* __restrict__ sums, const float* __restrict__ g,
                           const float* __restrict__ be, int do_elu,
                           unsigned k0, unsigned k1) {
    long long i = (long long)blockIdx.x * blockDim.x + threadIdx.x;
    long long total = (long long)N * C;
    if (i >= total) return;
    int c = (int)(i % C);
    float invN = 1.f / (float)N;
    float mu = sums[c] * invN;
    float var = sums[C + c] * invN - mu * mu;
    float v = x[i];
    float y = (v - mu) * rsqrtf(var + EPSV) * g[c] + be[c];
    if (do_elu) y = y > 0.f ? y : expm1f(y);
    unsigned bits = tf_xor(k0, k1, 0u, (unsigned)i);
    y = (bits & 0x80000000u) ? 0.f : 2.f * y;
    x[i] = y;
}

// ---------------- selection (nonzero + gather) ----------------
__global__ void k_cond(const float* __restrict__ x, int* __restrict__ flag, int n) {
    int i = blockIdx.x * blockDim.x + threadIdx.x;
    if (i < n) flag[i] = (x[i * 6 + 2] == 1.0f && x[i * 6 + 5] == 0.0f) ? 1 : 0;
}
__global__ void k_zero_int(int* p, int n) {
    int i = blockIdx.x * blockDim.x + threadIdx.x;
    if (i < n) p[i] = 0;
}
__global__ void k_idx_scatter(const int* __restrict__ flag, const int* __restrict__ pos,
                              int* __restrict__ idx, int n) {
    int i = blockIdx.x * blockDim.x + threadIdx.x;
    if (i < n && flag[i]) idx[pos[i]] = i;
}
__global__ void k_gather32(const float* __restrict__ src, const int* __restrict__ idx,
                           float* __restrict__ dst, int n) {
    int i = blockIdx.x * blockDim.x + threadIdx.x;
    if (i < n * 32) {
        int j = i >> 5, c = i & 31;
        dst[i] = src[(size_t)idx[j] * 32 + c];
    }
}

// ---------------- LayerNorm + ReLU (blockDim = C) ----------------
__global__ void k_ln_relu(float* __restrict__ x, int C, const float* __restrict__ g,
                          const float* __restrict__ b) {
    __shared__ float s1[128], s2[128];
    int n = blockIdx.x, t = threadIdx.x;
    float v = x[(size_t)n * C + t];
    s1[t] = v; s2[t] = v * v;
    __syncthreads();
    for (int o = blockDim.x >> 1; o > 0; o >>= 1) {
        if (t < o) { s1[t] += s1[t + o]; s2[t] += s2[t + o]; }
        __syncthreads();
    }
    float invC = 1.f / (float)C;
    float mu = s1[0] * invC;
    float var = s2[0] * invC - mu * mu;
    float y = (v - mu) * rsqrtf(var + EPSV) * g[t] + b[t];
    x[(size_t)n * C + t] = fmaxf(y, 0.f);
}

// ---------------- final head: tanh(a @ A3 + ab3) ----------------
__global__ void k_head(const float* __restrict__ a, const float* __restrict__ A3,
                       const float* __restrict__ ab3, float* __restrict__ logits, int n) {
    int gw = (blockIdx.x * blockDim.x + threadIdx.x) >> 5;
    int lane = threadIdx.x & 31;
    if (gw >= n) return;
    const float* ar = a + (size_t)gw * 64;
    float s = fmaf(ar[lane], A3[lane], ar[lane + 32] * A3[lane + 32]);
#pragma unroll
    for (int o = 16; o > 0; o >>= 1) s += __shfl_xor_sync(0xffffffffu, s, o);
    if (lane == 0) logits[gw] = tanhf(s + ab3[0]);
}

// ---------------- softmax reductions ----------------
__global__ void k_red_max(const float* __restrict__ x, int n, float* __restrict__ part) {
    __shared__ float sh[256];
    float m = -FLT_MAX;
    for (int i = blockIdx.x * blockDim.x + threadIdx.x; i < n; i += gridDim.x * blockDim.x)
        m = fmaxf(m, x[i]);
    sh[threadIdx.x] = m;
    __syncthreads();
    for (int o = 128; o > 0; o >>= 1) {
        if (threadIdx.x < o) sh[threadIdx.x] = fmaxf(sh[threadIdx.x], sh[threadIdx.x + o]);
        __syncthreads();
    }
    if (threadIdx.x == 0) part[blockIdx.x] = sh[0];
}
__global__ void k_red_max_fin(const float* __restrict__ part, float* __restrict__ scal) {
    __shared__ float sh[128];
    sh[threadIdx.x] = part[threadIdx.x];
    __syncthreads();
    for (int o = 64; o > 0; o >>= 1) {
        if (threadIdx.x < o) sh[threadIdx.x] = fmaxf(sh[threadIdx.x], sh[threadIdx.x + o]);
        __syncthreads();
    }
    if (threadIdx.x == 0) scal[0] = sh[0];
}
__global__ void k_red_sum(const float* __restrict__ x, int n, const float* __restrict__ scal,
                          float* __restrict__ part) {
    __shared__ float sh[256];
    float mx = scal[0];
    float s = 0.f;
    for (int i = blockIdx.x * blockDim.x + threadIdx.x; i < n; i += gridDim.x * blockDim.x)
        s += expf(x[i] - mx);
    sh[threadIdx.x] = s;
    __syncthreads();
    for (int o = 128; o > 0; o >>= 1) {
        if (threadIdx.x < o) sh[threadIdx.x] += sh[threadIdx.x + o];
        __syncthreads();
    }
    if (threadIdx.x == 0) part[blockIdx.x] = sh[0];
}
__global__ void k_red_sum_fin(const float* __restrict__ part, float* __restrict__ scal) {
    __shared__ float sh[128];
    sh[threadIdx.x] = part[threadIdx.x];
    __syncthreads();
    for (int o = 64; o > 0; o >>= 1) {
        if (threadIdx.x < o) sh[threadIdx.x] += sh[threadIdx.x + o];
        __syncthreads();
    }
    if (threadIdx.x == 0) scal[1] = sh[0];
}
__global__ void k_write_out(const float* __restrict__ logits, int n,
                            const float* __restrict__ scal, float* __restrict__ out) {
    int i = blockIdx.x * blockDim.x + threadIdx.x;
    if (i < n) {
        float l = logits[i];
        out[i] = l;
        out[n + i] = expf(l - scal[0]) / scal[1];
    }
}

// ---------------- launch ----------------
extern "C" void kernel_launch(void* const* d_in, const int* in_sizes, int n_in,
                              void* d_out, int out_size) {
    const float* x   = (const float*)d_in[0];
    const int* ei    = (const int*)d_in[1];
    int E = in_sizes[1] / 2;
    const int* esrc = ei;
    const int* edst = ei + E;
    const float* W1  = (const float*)d_in[2];
    const float* as1 = (const float*)d_in[3];
    const float* ad1 = (const float*)d_in[4];
    const float* b1  = (const float*)d_in[5];
    const float* g1  = (const float*)d_in[6];
    const float* be1 = (const float*)d_in[7];
    const float* W2  = (const float*)d_in[8];
    const float* as2 = (const float*)d_in[9];
    const float* ad2 = (const float*)d_in[10];
    const float* b2  = (const float*)d_in[11];
    const float* g2  = (const float*)d_in[12];
    const float* be2 = (const float*)d_in[13];
    const float* W3  = (const float*)d_in[14];
    const float* as3 = (const float*)d_in[15];
    const float* ad3 = (const float*)d_in[16];
    const float* b3  = (const float*)d_in[17];
    const float* g3  = (const float*)d_in[18];
    const float* be3 = (const float*)d_in[19];
    const float* A1  = (const float*)d_in[20];
    const float* ab1 = (const float*)d_in[21];
    const float* l1g = (const float*)d_in[22];
    const float* l1b = (const float*)d_in[23];
    const float* A2  = (const float*)d_in[24];
    const float* ab2 = (const float*)d_in[25];
    const float* l2g = (const float*)d_in[26];
    const float* l2b = (const float*)d_in[27];
    const float* A3  = (const float*)d_in[28];
    const float* ab3 = (const float*)d_in[29];

    float *h, *io0, *io1, *ls, *ld, *logits, *bn, *part, *scal;
    int *deg, *off, *cur, *srcs;
    cudaGetSymbolAddress((void**)&h, g_h);
    cudaGetSymbolAddress((void**)&io0, g_io0);
    cudaGetSymbolAddress((void**)&io1, g_io1);
    cudaGetSymbolAddress((void**)&ls, g_ls);
    cudaGetSymbolAddress((void**)&ld, g_ld);
    cudaGetSymbolAddress((void**)&logits, g_logits);
    cudaGetSymbolAddress((void**)&bn, g_bn);
    cudaGetSymbolAddress((void**)&part, g_part);
    cudaGetSymbolAddress((void**)&scal, g_scal);
    cudaGetSymbolAddress((void**)&deg, g_deg);
    cudaGetSymbolAddress((void**)&off, g_off);
    cudaGetSymbolAddress((void**)&cur, g_cur);
    cudaGetSymbolAddress((void**)&srcs, g_srcs);

    // dropout keys: jax.random.split(jax.random.key(42), 3), partitionable foldlike
    unsigned dk[3][2];
    for (unsigned i = 0; i < 3; i++) tf_host(0u, 42u, 0u, i, &dk[i][0], &dk[i][1]);

    const int nb = (NN + 255) / 256;

    // ---- CSR by dst (edges + self loops) ----
    k_init_deg<<<nb, 256>>>(deg, NN);
    k_count<<<(E + 255) / 256, 256>>>(edst, E, deg);
    k_exscan<<<1, 1024>>>(deg, off, NN);
    k_copy_int<<<nb, 256>>>(off, cur, NN);
    k_scatter<<<(E + NN + 255) / 256, 256>>>(esrc, edst, E, NN, cur, srcs);

    // ---- layer 1: in x[:,1:5] (K=4) -> 4x128 heads ----
    k_gemm16x2<<<NN / 16, 256, 4 * 16 * sizeof(float)>>>(x, 6, 1, W1, nullptr, h, 4, 512);
    k_attn_coef<<<NN, 128>>>(h, as1, ad1, ls, ld, 128);
    k_gat_aggregate<<<NN, 128>>>(h, ls, ld, off, srcs, b1, io0, 128);
    k_zero256<<<1, 256>>>(bn);
    k_bn_stats<<<nb, 128>>>(io0, NN, 128, bn);
    k_bn_apply<<<(NN * 128 + 255) / 256, 256>>>(io0, NN, 128, bn, g1, be1, 1, dk[0][0], dk[0][1]);

    // ---- layer 2: 128 -> 4x64 heads ----
    k_gemm16x2<<<NN / 16, 128, 128 * 16 * sizeof(float)>>>(io0, 128, 0, W2, nullptr, h, 128, 256);
    k_attn_coef<<<NN, 128>>>(h, as2, ad2, ls, ld, 64);
    k_gat_aggregate<<<NN, 64>>>(h, ls, ld, off, srcs, b2, io1, 64);
    k_zero256<<<1, 256>>>(bn);
    k_bn_stats<<<nb, 64>>>(io1, NN, 64, bn);
    k_bn_apply<<<(NN * 64 + 255) / 256, 256>>>(io1, NN, 64, bn, g2, be2, 1, dk[1][0], dk[1][1]);

    // ---- layer 3: 64 -> 4x32 heads, no ELU ----
    k_gemm16x2<<<NN / 16, 64, 64 * 16 * sizeof(float)>>>(io1, 64, 0, W3, nullptr, h, 64, 128);
    k_attn_coef<<<NN, 128>>>(h, as3, ad3, ls, ld, 32);
    k_gat_aggregate<<<NN, 32>>>(h, ls, ld, off, srcs, b3, io0, 32);
    k_zero256<<<1, 256>>>(bn);
    k_bn_stats<<<nb, 32>>>(io0, NN, 32, bn);
    k_bn_apply<<<(NN * 32 + 255) / 256, 256>>>(io0, NN, 32, bn, g3, be3, 0, dk[2][0], dk[2][1]);

    // ---- nonzero(cond, size=N, fill=0) + gather ----
    k_cond<<<nb, 256>>>(x, deg, NN);
    k_exscan<<<1, 1024>>>(deg, off, NN);
    k_zero_int<<<nb, 256>>>(cur, NN);
    k_idx_scatter<<<nb, 256>>>(deg, off, cur, NN);
    k_gather32<<<(NN * 32 + 255) / 256, 256>>>(io0, cur, io1, NN);

    // ---- MLP head ----
    k_gemm16x2<<<NN / 16, 64, 32 * 16 * sizeof(float)>>>(io1, 32, 0, A1, ab1, h, 32, 128);
    k_ln_relu<<<NN, 128>>>(h, 128, l1g, l1b);
    k_gemm16x2<<<NN / 16, 32, 128 * 16 * sizeof(float)>>>(h, 128, 0, A2, ab2, io0, 128, 64);
    k_ln_relu<<<NN, 64>>>(io0, 64, l2g, l2b);
    k_head<<<(NN * 32 + 255) / 256, 256>>>(io0, A3, ab3, logits, NN);

    // ---- softmax over all N ----
    k_red_max<<<128, 256>>>(logits, NN, part);
    k_red_max_fin<<<1, 128>>>(part, scal);
    k_red_sum<<<128, 256>>>(logits, NN, scal, part);
    k_red_sum_fin<<<1, 128>>>(part, scal);
    k_write_out<<<nb, 256>>>(logits, NN, scal, (float*)d_out);
}